// round 2
// baseline (speedup 1.0000x reference)
#include <cuda_runtime.h>
#include <cuda_bf16.h>
#include <cstddef>

// Problem dims
// x  : 131072 floats                  = (2048 ij, 64 m)
// Ci : 4194304 floats (512,4,512,4)   = (2048 ij, 2048 kl)   kl = cap*4 + rf
// Wi : 33554432 floats (512,4,4,64,64) -> flat b*16384 + k*4096 + l*64 + m, b = i*4+j
// y  : 131072 floats (512,4,64)       -> b*64 + l

#define N_IJ   2048
#define N_KL   2048
#define N_M    64
#define IJ_GRP 8          // ij split groups (partials)
#define IJ_PER 256        // ij per group
#define KLT    32         // kl per routing block
#define XR_N   131072     // 2048*64

// Partial routed activations: [IJ_GRP][kl][m]  (4 MB scratch, allowed as __device__)
__device__ float g_part[IJ_GRP * XR_N];

// ---------------------------------------------------------------------------
// Kernel 1: routing.  grid = 64 kl-tiles * 8 ij-groups = 512 blocks, 256 thr.
// Thread t owns kl_local = t>>3 (one kl), m = (t&7)*8 .. +8  (two float4 acc).
// Warp has 4 distinct kl -> if all 4 Ci values are 0 (p=0.66) the 16-FMA body
// is skipped coherently. Ci loads are fully coalesced (128B rows per warp).
// ---------------------------------------------------------------------------
__global__ void __launch_bounds__(256) route_kernel(const float* __restrict__ Ci,
                                                    const float* __restrict__ x)
{
    __shared__ float sC[64 * KLT];   // 8 KB
    __shared__ float sx[64 * N_M];   // 16 KB

    const int bx  = blockIdx.x;
    const int klt = bx >> 3;         // 0..63
    const int ijg = bx & 7;          // 0..7
    const int t   = threadIdx.x;
    const int kl_local = t >> 3;     // 0..31
    const int m_base   = (t & 7) * 8;

    const int ij0 = ijg * IJ_PER;
    const int kl0 = klt * KLT;

    float4 a0 = make_float4(0.f, 0.f, 0.f, 0.f);
    float4 a1 = make_float4(0.f, 0.f, 0.f, 0.f);

    for (int c0 = 0; c0 < IJ_PER; c0 += 64) {
        __syncthreads();
        // stage Ci tile: 64 ij x 32 kl (each warp loads one 128B row)
        #pragma unroll
        for (int p = 0; p < 8; p++) {
            int idx = t + p * 256;
            int r = idx >> 5, cc = idx & 31;
            sC[idx] = Ci[(size_t)(ij0 + c0 + r) * N_KL + kl0 + cc];
        }
        // stage x tile: 64 ij x 64 m, fully contiguous 16 KB
        #pragma unroll
        for (int p = 0; p < 16; p++) {
            int idx = t + p * 256;
            sx[idx] = x[(ij0 + c0) * N_M + idx];
        }
        __syncthreads();

        #pragma unroll 4
        for (int r = 0; r < 64; r++) {
            float c = sC[r * KLT + kl_local];
            if (c != 0.0f) {
                const float4* sp = reinterpret_cast<const float4*>(sx + r * N_M + m_base);
                float4 v0 = sp[0], v1 = sp[1];
                a0.x = fmaf(c, v0.x, a0.x);
                a0.y = fmaf(c, v0.y, a0.y);
                a0.z = fmaf(c, v0.z, a0.z);
                a0.w = fmaf(c, v0.w, a0.w);
                a1.x = fmaf(c, v1.x, a1.x);
                a1.y = fmaf(c, v1.y, a1.y);
                a1.z = fmaf(c, v1.z, a1.z);
                a1.w = fmaf(c, v1.w, a1.w);
            }
        }
    }

    // contiguous float4 stores: address = base + t*8 floats
    float4* out = reinterpret_cast<float4*>(
        &g_part[(size_t)ijg * XR_N + (size_t)(kl0 + kl_local) * N_M + m_base]);
    out[0] = a0;
    out[1] = a1;
}

// ---------------------------------------------------------------------------
// Kernel 2: per-capsule transform.  grid = 2048 blocks (b = i*4+j), 256 thr.
// Folds the 8-way partial reduction of xr into the smem load.
// Warp w computes l = w*8+q ; lane covers k in {ka, ka+2}, m in [mi*4, mi*4+4)
// via float4 loads (coalesced 256B segments), then warp shuffle-reduce.
// Wi streamed once (128 MB) -> HBM-bound.
// ---------------------------------------------------------------------------
__global__ void __launch_bounds__(256) transform_kernel(const float* __restrict__ Wi,
                                                        float* __restrict__ y)
{
    __shared__ float sxr[256];

    const int b = blockIdx.x;     // i*4 + j
    const int i = b >> 2;
    const int t = threadIdx.x;

    // xr[i, k, m] = sum of 8 ij-group partials
    float s = 0.f;
    #pragma unroll
    for (int g = 0; g < 8; g++)
        s += g_part[(size_t)g * XR_N + i * 256 + t];
    sxr[t] = s;
    __syncthreads();

    const int w  = t >> 5;
    const int L  = t & 31;
    const int ka = L >> 4;        // 0 or 1
    const int mi = L & 15;        // float4 index over m

    const float4* sxr4 = reinterpret_cast<const float4*>(sxr);
    const float4* W4   = reinterpret_cast<const float4*>(Wi + (size_t)b * 16384);

    #pragma unroll
    for (int q = 0; q < 8; q++) {
        const int l = w * 8 + q;
        float acc = 0.f;
        #pragma unroll
        for (int kk = 0; kk < 2; kk++) {
            const int k = ka + kk * 2;
            float4 v  = W4[(k * 4096 + l * 64) >> 2 | 0];  // base/4
            v = W4[((k * 4096 + l * 64) >> 2) + mi];
            float4 xv = sxr4[k * 16 + mi];
            acc = fmaf(v.x, xv.x, acc);
            acc = fmaf(v.y, xv.y, acc);
            acc = fmaf(v.z, xv.z, acc);
            acc = fmaf(v.w, xv.w, acc);
        }
        #pragma unroll
        for (int off = 16; off; off >>= 1)
            acc += __shfl_xor_sync(0xFFFFFFFFu, acc, off);
        if (L == 0) y[b * 64 + l] = acc;
    }
}

// ---------------------------------------------------------------------------
extern "C" void kernel_launch(void* const* d_in, const int* in_sizes, int n_in,
                              void* d_out, int out_size)
{
    const float* x  = nullptr;
    const float* Ci = nullptr;
    const float* Wi = nullptr;
    for (int i = 0; i < n_in; i++) {
        if (in_sizes[i] == 131072)        x  = (const float*)d_in[i];
        else if (in_sizes[i] == 4194304)  Ci = (const float*)d_in[i];
        else if (in_sizes[i] == 33554432) Wi = (const float*)d_in[i];
    }
    float* y = (float*)d_out;

    route_kernel<<<512, 256>>>(Ci, x);
    transform_kernel<<<2048, 256>>>(Wi, y);
}